// round 4
// baseline (speedup 1.0000x reference)
#include <cuda_runtime.h>
#include <cuda_bf16.h>
#include <stdint.h>

// Problem constants (fixed by the dataset)
#define NN 8192
#define DD 128
#define WORDS_PER_ROW 256          // 8192 bits / 32
#define MAXNNZ 128                 // per-row capacity (mean ~32; Poisson tail -> 128 is astronomically safe)

// -------- scratch (no allocations allowed) --------
__device__ __align__(16) uint32_t g_mask[NN * WORDS_PER_ROW];   // 8 MB adjacency bitmask (edges only, no eye)
__device__ __align__(16) int      g_list[NN * MAXNNZ];          // 4 MB compacted neighbor lists
__device__ __align__(16) int      g_nnz[NN];
__device__ __align__(16) float    g_dis[NN];                    // d^{-1/2}
__device__ __align__(16) float    g_ys[NN * DD];                // ys[j] = dis[j] * (x @ W^T)[j]
__device__ int g_is64;                                          // edge_index dtype flag (auto-detected)

// K0: detect whether edge_index is int64 or int32.
// Values are < 8192, so for int64 (little-endian) every odd 32-bit word is 0.
__global__ void k_detect(const uint32_t* __restrict__ raw) {
    if (threadIdx.x == 0 && blockIdx.x == 0) {
        int is64 = 1;
        #pragma unroll 1
        for (int i = 1; i < 256; i += 2)
            if (raw[i] != 0u) { is64 = 0; break; }
        g_is64 = is64;
    }
}

// K1: zero the bitmask (must rerun every graph replay)
__global__ void k_zero_mask() {
    uint4* p = reinterpret_cast<uint4*>(g_mask);
    int total = NN * WORDS_PER_ROW / 4;
    for (int i = blockIdx.x * blockDim.x + threadIdx.x; i < total; i += gridDim.x * blockDim.x)
        p[i] = make_uint4(0u, 0u, 0u, 0u);
}

// K2: scatter edges into the bitmask (atomicOr dedups for free).
// Indices are masked to [0, NN) so a bad interpretation can never fault.
__global__ void k_scatter(const void* __restrict__ eiraw, int E) {
    int e = blockIdx.x * blockDim.x + threadIdx.x;
    if (e >= E) return;
    int r, c;
    if (g_is64) {
        const long long* ei = (const long long*)eiraw;
        r = (int)ei[e];
        c = (int)ei[E + e];
    } else {
        const int* ei = (const int*)eiraw;
        r = ei[e];
        c = ei[E + e];
    }
    r &= (NN - 1);
    c &= (NN - 1);
    atomicOr(&g_mask[r * WORDS_PER_ROW + (c >> 5)], 1u << (c & 31));
}

// K3: per-row degree + d^{-1/2} + compact bit indices into g_list.
// One warp per row; lane handles words {lane, lane+32, ...} (8 words).
__global__ void k_degree_extract() {
    int gwarp = (blockIdx.x * blockDim.x + threadIdx.x) >> 5;
    int lane  = threadIdx.x & 31;
    if (gwarp >= NN) return;
    const uint32_t* row = g_mask + gwarp * WORDS_PER_ROW;
    int* out = g_list + gwarp * MAXNNZ;
    int base = 0;
    #pragma unroll
    for (int w8 = 0; w8 < 8; w8++) {
        int widx = w8 * 32 + lane;
        uint32_t word = row[widx];
        int c = __popc(word);
        // inclusive warp scan
        int pre = c;
        #pragma unroll
        for (int o = 1; o < 32; o <<= 1) {
            int v = __shfl_up_sync(0xFFFFFFFFu, pre, o);
            if (lane >= o) pre += v;
        }
        int tot = __shfl_sync(0xFFFFFFFFu, pre, 31);
        pre -= c;                      // exclusive
        int pos = base + pre;
        while (word) {
            int b = __ffs(word) - 1;
            word &= word - 1;
            if (pos < MAXNNZ) out[pos] = widx * 32 + b;
            pos++;
        }
        base += tot;
    }
    if (lane == 0) {
        g_nnz[gwarp] = base > MAXNNZ ? MAXNNZ : base;
        // degree = popcount(row) + 1 (the +eye; a self-edge bit already counted -> diag 2 handled)
        g_dis[gwarp] = rsqrtf((float)(base + 1));
    }
}

// K4: ys = diag(dis) * (x @ W^T).  M=8192, N=128, K=128 fp32.
// Block: 128 threads (32x4); each thread: 4 features x 8 rows register tile.
__global__ void k_gemm_xw(const float* __restrict__ x, const float* __restrict__ W) {
    __shared__ float sW[64 * 129];   // sW[k*129 + f] : conflict-free for both store & load
    __shared__ float sx[32 * 64];    // sx[r*64 + k]  : broadcast reads
    int t  = threadIdx.x;
    int tx = t & 31;                 // feature lane
    int ty = t >> 5;                 // row group
    int r0 = blockIdx.x * 32;

    float acc[4][8];
    #pragma unroll
    for (int q = 0; q < 4; q++)
        #pragma unroll
        for (int p = 0; p < 8; p++) acc[q][p] = 0.f;

    for (int ch = 0; ch < 2; ch++) {
        __syncthreads();
        for (int i = t; i < 128 * 64; i += 128) {       // sW[k][f] = W[f][ch*64+k]
            int f = i >> 6, k = i & 63;
            sW[k * 129 + f] = W[f * 128 + ch * 64 + k];
        }
        for (int i = t; i < 32 * 64; i += 128) {        // sx[r][k] = x[r0+r][ch*64+k]
            int r = i >> 6, k = i & 63;
            sx[r * 64 + k] = x[(r0 + r) * 128 + ch * 64 + k];
        }
        __syncthreads();
        #pragma unroll 8
        for (int k = 0; k < 64; k++) {
            float wv[4];
            #pragma unroll
            for (int q = 0; q < 4; q++) wv[q] = sW[k * 129 + tx + 32 * q];
            #pragma unroll
            for (int p = 0; p < 8; p++) {
                float xv = sx[(ty + 4 * p) * 64 + k];
                #pragma unroll
                for (int q = 0; q < 4; q++) acc[q][p] += xv * wv[q];
            }
        }
    }
    #pragma unroll
    for (int p = 0; p < 8; p++) {
        int r = r0 + ty + 4 * p;
        float d = g_dis[r];
        #pragma unroll
        for (int q = 0; q < 4; q++)
            g_ys[r * 128 + tx + 32 * q] = d * acc[q][p];
    }
}

// K5: out[i] = dis[i] * ( sum_{j in list(i)} ys[j] + ys[i] ) + b
// (the "+ ys[i]" is the +eye diagonal term; a self-edge bit already in the list -> diag 2 correct)
__global__ void k_aggregate(const float* __restrict__ bias, float* __restrict__ out) {
    int i = blockIdx.x;
    int t = threadIdx.x;
    __shared__ int sj[MAXNNZ];
    int nn = g_nnz[i];
    if (t < nn) sj[t] = g_list[i * MAXNNZ + t];
    __syncthreads();
    float acc = g_ys[i * 128 + t];
    int n = 0;
    for (; n + 4 <= nn; n += 4) {
        int j0 = sj[n], j1 = sj[n + 1], j2 = sj[n + 2], j3 = sj[n + 3];
        float a0 = g_ys[j0 * 128 + t];
        float a1 = g_ys[j1 * 128 + t];
        float a2 = g_ys[j2 * 128 + t];
        float a3 = g_ys[j3 * 128 + t];
        acc += (a0 + a1) + (a2 + a3);
    }
    for (; n < nn; n++) acc += g_ys[sj[n] * 128 + t];
    out[i * 128 + t] = g_dis[i] * acc + bias[t];
}

extern "C" void kernel_launch(void* const* d_in, const int* in_sizes, int n_in,
                              void* d_out, int out_size) {
    const float* x  = (const float*)d_in[0];
    const void*  ei = d_in[1];
    const float* W  = (const float*)d_in[2];
    const float* b  = (const float*)d_in[3];
    float* out = (float*)d_out;
    int E = in_sizes[1] / 2;   // element count of edge_index / 2, dtype-independent

    k_detect<<<1, 32>>>((const uint32_t*)ei);
    k_zero_mask<<<512, 256>>>();
    k_scatter<<<(E + 255) / 256, 256>>>(ei, E);
    k_degree_extract<<<NN / 8, 256>>>();            // 8 warps/block, warp per row
    k_gemm_xw<<<NN / 32, 128>>>(x, W);
    k_aggregate<<<NN, 128>>>(b, out);
}